// round 1
// baseline (speedup 1.0000x reference)
#include <cuda_runtime.h>

// Convex upsampling (RAFT-style): softmax(mask over 9 taps) * unfold3x3(4*flow),
// upsampled 4x4 per pixel.
//
// Shapes (fixed by setup_inputs):
//   flow: (4, 1, 160, 320) f32
//   mask: (4, 144, 160, 320) f32   where 144 = 9 taps * 4 * 4 subpixels
//   out:  (4, 1, 640, 1280) f32
//
// mask channel index for tap k, subpixel (fy,fx):  c = k*16 + fy*4 + fx
// out[n, 4h+fy, 4w+fx] = sum_k softmax_k(mask[n, k*16+fy*4+fx, h, w]) * 4*flow_window_k

#define NN 4
#define HH 160
#define WW 320
#define FF 4
#define OW (WW * FF)   // 1280
#define PLANE (HH * WW)

__global__ __launch_bounds__(256) void convex_upsample_kernel(
    const float* __restrict__ flow,
    const float* __restrict__ mask,
    float* __restrict__ out)
{
    int idx = blockIdx.x * blockDim.x + threadIdx.x;
    if (idx >= NN * HH * WW) return;

    int w = idx % WW;
    int h = (idx / WW) % HH;
    int n = idx / (WW * HH);

    // ---- 3x3 flow window, zero-padded, scaled by FACTOR=4 ----
    const float* fp = flow + (size_t)n * PLANE;
    float fv[9];
#pragma unroll
    for (int dy = 0; dy < 3; dy++) {
#pragma unroll
        for (int dx = 0; dx < 3; dx++) {
            int hh = h + dy - 1;
            int ww = w + dx - 1;
            float v = 0.0f;
            if (hh >= 0 && hh < HH && ww >= 0 && ww < WW)
                v = 4.0f * fp[hh * WW + ww];
            fv[dy * 3 + dx] = v;
        }
    }

    // mask base for this (n, h, w); channel stride = PLANE
    const float* mp = mask + (size_t)n * 144 * PLANE + (size_t)h * WW + w;
    float* op = out + (size_t)n * (FF * HH) * OW;

#pragma unroll
    for (int fy = 0; fy < FF; fy++) {
        float r[FF];
#pragma unroll
        for (int fx = 0; fx < FF; fx++) {
            int c0 = fy * FF + fx;           // base channel, taps at stride 16
            float mv[9];
#pragma unroll
            for (int k = 0; k < 9; k++)
                mv[k] = mp[(size_t)(c0 + k * 16) * PLANE];

            float mx = mv[0];
#pragma unroll
            for (int k = 1; k < 9; k++) mx = fmaxf(mx, mv[k]);

            float s = 0.0f, acc = 0.0f;
#pragma unroll
            for (int k = 0; k < 9; k++) {
                float e = __expf(mv[k] - mx);
                s += e;
                acc = fmaf(e, fv[k], acc);
            }
            r[fx] = acc / s;
        }
        float4 v4 = make_float4(r[0], r[1], r[2], r[3]);
        *reinterpret_cast<float4*>(op + (size_t)(h * FF + fy) * OW + w * FF) = v4;
    }
}

extern "C" void kernel_launch(void* const* d_in, const int* in_sizes, int n_in,
                              void* d_out, int out_size)
{
    const float* flow = (const float*)d_in[0];
    const float* mask = (const float*)d_in[1];
    float* out = (float*)d_out;

    const int total = NN * HH * WW;           // 204800 threads
    const int threads = 256;
    const int blocks = (total + threads - 1) / threads;
    convex_upsample_kernel<<<blocks, threads>>>(flow, mask, out);
}